// round 15
// baseline (speedup 1.0000x reference)
#include <cuda_runtime.h>
#include <cuda_fp16.h>
#include <cstdint>

#define B_    8
#define C_    128
#define N_    4096
#define M_    4096
#define OUT_  128
#define LOG2E 1.4426950408889634f

// single shared-mem declaration for the whole TU (nvcc requires consistency)
extern __shared__ char dyn_smem[];

// ---------------------------------------------------------------------------
// static device scratch (allocation-free)
// ---------------------------------------------------------------------------
__device__ __half g_qh[(size_t)B_ * M_ * C_];   // [b][m][c] normalized*log2e (fp16)
__device__ __half g_kh[(size_t)B_ * N_ * C_];   // [b][n][c] normalized (fp16)
__device__ __half g_vh[(size_t)B_ * C_ * N_];   // [b][c][n] raw fp16
__device__ __half g_wh[C_ * OUT_];              // [o][c] weight hi (transposed for MMA B)
__device__ __half g_wl[C_ * OUT_];              // [o][c] weight residual
__device__ float  g_sc[OUT_];                   // BN scale
__device__ float  g_bi[OUT_];                   // BN bias

// ---------------------------------------------------------------------------
// helpers (base-ISA only: ldmatrix / mma.sync / cp.async)
// ---------------------------------------------------------------------------
__device__ __forceinline__ uint32_t smem_u32(const void* p) {
    uint32_t a;
    asm("{ .reg .u64 t; cvta.to.shared.u64 t, %1; cvt.u32.u64 %0, t; }" : "=r"(a) : "l"(p));
    return a;
}
__device__ __forceinline__ void ldsm4(uint32_t* r, uint32_t addr) {
    asm volatile("ldmatrix.sync.aligned.m8n8.x4.shared.b16 {%0,%1,%2,%3}, [%4];"
                 : "=r"(r[0]), "=r"(r[1]), "=r"(r[2]), "=r"(r[3]) : "r"(addr));
}
__device__ __forceinline__ void mma16816(float* d, const uint32_t* a, const uint32_t* b) {
    asm volatile("mma.sync.aligned.m16n8k16.row.col.f32.f16.f16.f32 "
                 "{%0,%1,%2,%3}, {%4,%5,%6,%7}, {%8,%9}, {%0,%1,%2,%3};"
                 : "+f"(d[0]), "+f"(d[1]), "+f"(d[2]), "+f"(d[3])
                 : "r"(a[0]), "r"(a[1]), "r"(a[2]), "r"(a[3]), "r"(b[0]), "r"(b[1]));
}
__device__ __forceinline__ void mma16816_h(uint32_t* d, const uint32_t* a, const uint32_t* b) {
    asm volatile("mma.sync.aligned.m16n8k16.row.col.f16.f16.f16.f16 "
                 "{%0,%1}, {%2,%3,%4,%5}, {%6,%7}, {%0,%1};"
                 : "+r"(d[0]), "+r"(d[1])
                 : "r"(a[0]), "r"(a[1]), "r"(a[2]), "r"(a[3]), "r"(b[0]), "r"(b[1]));
}
__device__ __forceinline__ void cpasync16(uint32_t saddr, const void* gaddr) {
    asm volatile("cp.async.cg.shared.global [%0], [%1], 16;" :: "r"(saddr), "l"(gaddr));
}
#define CP_COMMIT() asm volatile("cp.async.commit_group;" ::: "memory")
#define CP_WAIT1()  asm volatile("cp.async.wait_group 1;" ::: "memory")
__device__ __forceinline__ uint32_t pack_h2(float lo, float hi) {
    __half2 h = __floats2half2_rn(lo, hi);   // lo -> low 16 bits
    return *(uint32_t*)&h;
}
__device__ __forceinline__ uint32_t ex2_h2(uint32_t x) {
    uint32_t r;
    asm("ex2.approx.f16x2 %0, %1;" : "=r"(r) : "r"(x));
    return r;
}
__device__ __forceinline__ uint32_t hadd2_(uint32_t a, uint32_t b) {
    uint32_t r;
    asm("add.f16x2 %0, %1, %2;" : "=r"(r) : "r"(a), "r"(b));
    return r;
}
__device__ __forceinline__ float2 h2_to_f2(uint32_t a) {
    __half2 h = *(__half2*)&a;
    return __half22float2(h);
}

// ---------------------------------------------------------------------------
// merged prep kernel (block-range dispatch):
//  blocks [0,256):      tg -> g_qh (normalize over C, transpose, *LOG2E, fp16)
//  blocks [256,512):    input -> g_kh (normalize, transpose, fp16)
//  blocks [512,1536):   input -> g_vh (fp16 convert, layout preserved)
//  blocks [1536,1600):  weight -> g_wh/g_wl ([o][c] hi/lo) + BN constants
// ---------------------------------------------------------------------------
__global__ __launch_bounds__(256, 1)
void prep_all(const float* __restrict__ input, const float* __restrict__ tg,
              const float* __restrict__ w, const float* __restrict__ gamma,
              const float* __restrict__ beta, const float* __restrict__ rmean,
              const float* __restrict__ rvar) {
    int blk = blockIdx.x;
    int tid = threadIdx.x;

    if (blk < 512) {
        const float* x;
        __half* dst;
        float esc;
        int lb;
        if (blk < 256) { x = tg;    dst = g_qh; esc = LOG2E; lb = blk; }
        else           { x = input; dst = g_kh; esc = 1.0f;  lb = blk - 256; }
        float* t  = (float*)dyn_smem;              // [128][129]
        float* rn = t + 128 * 129;
        int b = lb >> 5, l0 = (lb & 31) * 128;
        const float* src = x + (size_t)b * C_ * 4096 + l0;
        for (int idx = tid; idx < 128 * 128; idx += 256) {
            int c = idx >> 7, l = idx & 127;
            t[c * 129 + l] = src[(size_t)c * 4096 + l];
        }
        __syncthreads();
        if (tid < 128) {
            float s = 0.f;
#pragma unroll 8
            for (int c = 0; c < 128; c++) { float v = t[c * 129 + tid]; s += v * v; }
            rn[tid] = esc / fmaxf(sqrtf(s), 1e-12f);
        }
        __syncthreads();
        for (int idx = tid; idx < 128 * 128; idx += 256) {
            int l = idx >> 7, c = idx & 127;
            float v = t[c * 129 + l] * rn[l];
            dst[((size_t)b * 4096 + l0 + l) * C_ + c] = __float2half_rn(v);
        }
    } else if (blk < 1536) {
        size_t i = (size_t)(blk - 512) * 256 + tid;
        for (; i < (size_t)B_ * C_ * N_ / 4; i += 1024 * 256) {
            float4 v = ((const float4*)input)[i];
            ((uint2*)g_vh)[i] = make_uint2(pack_h2(v.x, v.y), pack_h2(v.z, v.w));
        }
    } else {
        int i = (blk - 1536) * 256 + tid;       // 0 .. 16383
        if (i < C_ * OUT_) {
            int c = i / OUT_, o = i % OUT_;     // w is [c][o]; read coalesced
            float v = w[i];
            __half h = __float2half_rn(v);
            g_wh[o * C_ + c] = h;               // store [o][c]
            g_wl[o * C_ + c] = __float2half_rn(v - __half2float(h));
        }
        if (i < OUT_) {
            float s = rsqrtf(rvar[i] + 1e-5f) * gamma[i];
            g_sc[i] = s;
            g_bi[i] = beta[i] - rmean[i] * s;
        }
    }
}

// ---------------------------------------------------------------------------
// Pure-fp16 HMMA flash attention + fused projection/LeakyReLU/BN epilogue.
// grid = B*(M/128)=256, 256 threads (8 warps, 16 m-rows each).
// N-tile 128, double-buffered K/V via cp.async. Q fragments register-resident.
// S accumulated in fp16 (pre-packed for ex2/A-frag reuse); exp JIT in O-loop.
// smem: Q 32K | 2 x { K 32K | V 32K } | Whi 32K | Wlo 32K = 224K, 1 CTA/SM
// ---------------------------------------------------------------------------
#define SMQ  0
#define SMKV 32768
#define SMWH 163840
#define SMWL 196608
#define ATTN_SMEM 229376

__global__ __launch_bounds__(256, 1)
void attn_mma_kernel(float* __restrict__ out) {
    char* smc = dyn_smem;
    uint32_t sbase = smem_u32(smc);

    int tid = threadIdx.x;
    int w = tid >> 5, ln = tid & 31;
    int b  = blockIdx.x >> 5;
    int m0 = (blockIdx.x & 31) * 128;

    // ---- load Q tile [128m][128c] and W hi/lo [128o][128c] (once) ----
    {
        const uint4* qg = (const uint4*)(g_qh + ((size_t)b * M_ + m0) * C_);
        const uint4* whg = (const uint4*)g_wh;
        const uint4* wlg = (const uint4*)g_wl;
        for (int idx = tid; idx < 2048; idx += 256) {
            int row = idx >> 4, ch = idx & 15;
            uint32_t off = row * 256 + ((ch ^ (row & 7)) << 4);
            *(uint4*)(smc + SMQ + off)  = qg[row * 16 + ch];
            *(uint4*)(smc + SMWH + off) = whg[row * 16 + ch];
            *(uint4*)(smc + SMWL + off) = wlg[row * 16 + ch];
        }
    }

    // tile loader: K [128n][128c] + V [128c][128n], both 256B rows
    auto issue_tiles = [&](int buf, int it) {
        int n0 = it * 128;
        uint32_t kb = sbase + SMKV + buf * 65536;
        const char* kg = (const char*)(g_kh + ((size_t)b * N_ + n0) * C_);
#pragma unroll
        for (int i = 0; i < 8; i++) {
            int idx = tid + i * 256;
            int row = idx >> 4, ch = idx & 15;
            uint32_t off = row * 256 + ((ch ^ (row & 7)) << 4);
            cpasync16(kb + off, kg + row * 256 + ch * 16);
        }
        const char* vg = (const char*)(g_vh + (size_t)b * C_ * N_ + n0);
#pragma unroll
        for (int i = 0; i < 8; i++) {
            int idx = tid + i * 256;
            int row = idx >> 4, ch = idx & 15;
            uint32_t off = row * 256 + ((ch ^ (row & 7)) << 4);
            cpasync16(kb + 32768 + off, vg + (size_t)row * 8192 + ch * 16);
        }
    };

    issue_tiles(0, 0);
    CP_COMMIT();
    __syncthreads();      // Q smem stores visible

    // ---- hoist Q fragments to registers for the whole kernel ----
    uint32_t qfrag[8][4];
#pragma unroll
    for (int ks = 0; ks < 8; ks++) {
        int r = 16 * w + (ln & 15);
        int ch = 2 * ks + (ln >> 4);
        uint32_t off = r * 256 + ((ch ^ (r & 7)) << 4);
        ldsm4(qfrag[ks], sbase + SMQ + off);
    }

    float oacc[16][4];
#pragma unroll
    for (int i = 0; i < 16; i++)
#pragma unroll
        for (int j = 0; j < 4; j++) oacc[i][j] = 0.f;
    float rs0 = 0.f, rs1 = 0.f;

    for (int it = 0; it < 32; it++) {
        int buf = it & 1;
        __syncthreads();                       // prev reads of buf^1 done
        if (it + 1 < 32) issue_tiles(buf ^ 1, it + 1);
        CP_COMMIT();
        CP_WAIT1();                            // tile `it` landed
        __syncthreads();

        uint32_t kbase = sbase + SMKV + buf * 65536;
        uint32_t vbase = kbase + 32768;

        // ---- S = Q.K^T  [16m x 128n per warp], fp16 accumulators ----
        uint32_t s16[16][2];
#pragma unroll
        for (int i = 0; i < 16; i++) { s16[i][0] = 0u; s16[i][1] = 0u; }

#pragma unroll
        for (int ks = 0; ks < 8; ks++) {
#pragma unroll
            for (int p = 0; p < 8; p++) {
                uint32_t bh[4];
                int r = 16 * p + ((ln >> 4) << 3) + (ln & 7);
                int ch = 2 * ks + ((ln >> 3) & 1);
                uint32_t off = r * 256 + ((ch ^ (r & 7)) << 4);
                ldsm4(bh, kbase + off);
                mma16816_h(s16[2*p],   qfrag[ks], bh);
                mma16816_h(s16[2*p+1], qfrag[ks], bh + 2);
            }
        }

        // ---- O += exp2(S).V^T  (exp JIT per n-chunk; rowsum on the fly) ----
#pragma unroll
        for (int kn = 0; kn < 8; kn++) {
            uint32_t ah[4];
            ah[0] = ex2_h2(s16[2*kn][0]);
            ah[1] = ex2_h2(s16[2*kn][1]);
            ah[2] = ex2_h2(s16[2*kn+1][0]);
            ah[3] = ex2_h2(s16[2*kn+1][1]);
            float2 f0 = h2_to_f2(hadd2_(ah[0], ah[2]));
            rs0 += f0.x + f0.y;
            float2 f1 = h2_to_f2(hadd2_(ah[1], ah[3]));
            rs1 += f1.x + f1.y;
#pragma unroll
            for (int g = 0; g < 2; g++) {
#pragma unroll
                for (int p = 0; p < 4; p++) {
                    uint32_t vh[4];
                    int r = 16 * (4 * g + p) + ((ln >> 4) << 3) + (ln & 7);
                    int ch = 2 * kn + ((ln >> 3) & 1);
                    uint32_t off = r * 256 + ((ch ^ (r & 7)) << 4);
                    ldsm4(vh, vbase + off);
                    int cb = 8 * g + 2 * p;
                    mma16816(oacc[cb],     ah, vh);
                    mma16816(oacc[cb + 1], ah, vh + 2);
                }
            }
        }
    }

    // =================== fused epilogue ===================
    rs0 += __shfl_xor_sync(0xffffffffu, rs0, 1);
    rs0 += __shfl_xor_sync(0xffffffffu, rs0, 2);
    rs1 += __shfl_xor_sync(0xffffffffu, rs1, 1);
    rs1 += __shfl_xor_sync(0xffffffffu, rs1, 2);
    float inv0 = 1.0f / rs0, inv1 = 1.0f / rs1;

    // pack O/l hi + residual lo (same frag layout as mainloop P)
    uint32_t ohi[16][2], olo[16][2];
#pragma unroll
    for (int nb = 0; nb < 16; nb++) {
        float e0 = oacc[nb][0] * inv0;
        float e1 = oacc[nb][1] * inv0;
        float e2 = oacc[nb][2] * inv1;
        float e3 = oacc[nb][3] * inv1;
        __half h0 = __float2half_rn(e0), h1 = __float2half_rn(e1);
        __half h2 = __float2half_rn(e2), h3 = __float2half_rn(e3);
        ohi[nb][0] = (uint32_t)*(unsigned short*)&h0 | ((uint32_t)*(unsigned short*)&h1 << 16);
        ohi[nb][1] = (uint32_t)*(unsigned short*)&h2 | ((uint32_t)*(unsigned short*)&h3 << 16);
        olo[nb][0] = pack_h2(e0 - __half2float(h0), e1 - __half2float(h1));
        olo[nb][1] = pack_h2(e2 - __half2float(h2), e3 - __half2float(h3));
    }

    // epi MMA: z[16m][128o] = (O/l) . W   (W tile is [o][c]: B rows = o, cols = c)
    float eacc[16][4];
#pragma unroll
    for (int i = 0; i < 16; i++)
#pragma unroll
        for (int j = 0; j < 4; j++) eacc[i][j] = 0.f;

#pragma unroll
    for (int kc = 0; kc < 8; kc++) {
        uint32_t ah[4] = {ohi[2*kc][0], ohi[2*kc][1], ohi[2*kc+1][0], ohi[2*kc+1][1]};
        uint32_t al[4] = {olo[2*kc][0], olo[2*kc][1], olo[2*kc+1][0], olo[2*kc+1][1]};
#pragma unroll
        for (int p = 0; p < 8; p++) {
            int r = 16 * p + ((ln >> 4) << 3) + (ln & 7);
            int ch = 2 * kc + ((ln >> 3) & 1);
            uint32_t off = r * 256 + ((ch ^ (r & 7)) << 4);
            uint32_t wh[4], wl[4];
            ldsm4(wh, sbase + SMWH + off);
            ldsm4(wl, sbase + SMWL + off);
            mma16816(eacc[2*p],   ah, wh);
            mma16816(eacc[2*p+1], ah, wh + 2);
            mma16816(eacc[2*p],   ah, wl);
            mma16816(eacc[2*p+1], ah, wl + 2);
            mma16816(eacc[2*p],   al, wh);
            mma16816(eacc[2*p+1], al, wh + 2);
        }
    }

    // LeakyReLU + BN, scatter to stage [128o][132m] (reuses KV smem)
    __syncthreads();            // all warps done with last V tile before overwrite
    float* stage = (float*)(smc + SMKV);
    int r0 = 16 * w + (ln >> 2);
    int r1 = r0 + 8;
#pragma unroll
    for (int cb = 0; cb < 16; cb++) {
        int o0c = 8 * cb + 2 * (ln & 3);
        float s0 = g_sc[o0c],     b0 = g_bi[o0c];
        float s1 = g_sc[o0c + 1], b1 = g_bi[o0c + 1];
        float z0 = eacc[cb][0]; z0 = (z0 >= 0.f) ? z0 : 0.01f * z0;
        float z1 = eacc[cb][1]; z1 = (z1 >= 0.f) ? z1 : 0.01f * z1;
        float z2 = eacc[cb][2]; z2 = (z2 >= 0.f) ? z2 : 0.01f * z2;
        float z3 = eacc[cb][3]; z3 = (z3 >= 0.f) ? z3 : 0.01f * z3;
        stage[o0c * 132 + r0]       = z0 * s0 + b0;
        stage[(o0c + 1) * 132 + r0] = z1 * s1 + b1;
        stage[o0c * 132 + r1]       = z2 * s0 + b0;
        stage[(o0c + 1) * 132 + r1] = z3 * s1 + b1;
    }
    __syncthreads();

    // coalesced write: out[b][o][m0 + m]
    float* dst = out + ((size_t)b * OUT_) * M_ + m0;
    for (int idx = tid; idx < 128 * 32; idx += 256) {
        int o = idx >> 5, m4 = idx & 31;
        *(float4*)(dst + (size_t)o * M_ + 4 * m4) = *(float4*)(stage + o * 132 + 4 * m4);
    }
}

// ---------------------------------------------------------------------------
extern "C" void kernel_launch(void* const* d_in, const int* in_sizes, int n_in,
                              void* d_out, int out_size) {
    const float* input  = (const float*)d_in[0];
    const float* tg     = (const float*)d_in[1];
    const float* weight = (const float*)d_in[2];
    const float* gamma  = (const float*)d_in[3];
    const float* beta   = (const float*)d_in[4];
    const float* rmean  = (const float*)d_in[5];
    const float* rvar   = (const float*)d_in[6];
    float* out = (float*)d_out;

    const int prep_smem = (128 * 129 + 128) * (int)sizeof(float);
    cudaFuncSetAttribute(prep_all, cudaFuncAttributeMaxDynamicSharedMemorySize, prep_smem);
    cudaFuncSetAttribute(attn_mma_kernel, cudaFuncAttributeMaxDynamicSharedMemorySize, ATTN_SMEM);

    prep_all<<<1600, 256, prep_smem>>>(input, tg, weight, gamma, beta, rmean, rvar);
    attn_mma_kernel<<<B_ * (M_ / 128), 256, ATTN_SMEM>>>(out);
}

// round 16
// speedup vs baseline: 1.4696x; 1.4696x over previous
#include <cuda_runtime.h>
#include <cuda_fp16.h>
#include <cstdint>

#define B_    8
#define C_    128
#define N_    4096
#define M_    4096
#define OUT_  128
#define LOG2E 1.4426950408889634f

// single shared-mem declaration for the whole TU (nvcc requires consistency)
extern __shared__ char dyn_smem[];

// ---------------------------------------------------------------------------
// static device scratch (allocation-free)
// ---------------------------------------------------------------------------
__device__ __half g_qh[(size_t)B_ * M_ * C_];   // [b][m][c] normalized*log2e (fp16)
__device__ __half g_kh[(size_t)B_ * N_ * C_];   // [b][n][c] normalized (fp16)
__device__ __half g_vh[(size_t)B_ * C_ * N_];   // [b][c][n] raw fp16
__device__ __half g_wh[C_ * OUT_];              // [o][c] weight hi (transposed for MMA B)
__device__ __half g_wl[C_ * OUT_];              // [o][c] weight residual
__device__ float  g_sc[OUT_];                   // BN scale
__device__ float  g_bi[OUT_];                   // BN bias

// ---------------------------------------------------------------------------
// helpers (base-ISA only: ldmatrix / mma.sync / cp.async)
// ---------------------------------------------------------------------------
__device__ __forceinline__ uint32_t smem_u32(const void* p) {
    uint32_t a;
    asm("{ .reg .u64 t; cvta.to.shared.u64 t, %1; cvt.u32.u64 %0, t; }" : "=r"(a) : "l"(p));
    return a;
}
__device__ __forceinline__ void ldsm4(uint32_t* r, uint32_t addr) {
    asm volatile("ldmatrix.sync.aligned.m8n8.x4.shared.b16 {%0,%1,%2,%3}, [%4];"
                 : "=r"(r[0]), "=r"(r[1]), "=r"(r[2]), "=r"(r[3]) : "r"(addr));
}
__device__ __forceinline__ void mma16816(float* d, const uint32_t* a, const uint32_t* b) {
    asm volatile("mma.sync.aligned.m16n8k16.row.col.f32.f16.f16.f32 "
                 "{%0,%1,%2,%3}, {%4,%5,%6,%7}, {%8,%9}, {%0,%1,%2,%3};"
                 : "+f"(d[0]), "+f"(d[1]), "+f"(d[2]), "+f"(d[3])
                 : "r"(a[0]), "r"(a[1]), "r"(a[2]), "r"(a[3]), "r"(b[0]), "r"(b[1]));
}
__device__ __forceinline__ void cpasync16(uint32_t saddr, const void* gaddr) {
    asm volatile("cp.async.cg.shared.global [%0], [%1], 16;" :: "r"(saddr), "l"(gaddr));
}
#define CP_COMMIT() asm volatile("cp.async.commit_group;" ::: "memory")
#define CP_WAIT1()  asm volatile("cp.async.wait_group 1;" ::: "memory")
__device__ __forceinline__ uint32_t pack_h2(float lo, float hi) {
    __half2 h = __floats2half2_rn(lo, hi);   // lo -> low 16 bits
    return *(uint32_t*)&h;
}
__device__ __forceinline__ uint32_t ex2_h2(uint32_t x) {
    uint32_t r;
    asm("ex2.approx.f16x2 %0, %1;" : "=r"(r) : "r"(x));
    return r;
}
__device__ __forceinline__ uint32_t hadd2_(uint32_t a, uint32_t b) {
    uint32_t r;
    asm("add.f16x2 %0, %1, %2;" : "=r"(r) : "r"(a), "r"(b));
    return r;
}
__device__ __forceinline__ float2 h2_to_f2(uint32_t a) {
    __half2 h = *(__half2*)&a;
    return __half22float2(h);
}

// ---------------------------------------------------------------------------
// merged prep kernel (block-range dispatch):
//  blocks [0,256):      tg -> g_qh (normalize over C, transpose, *LOG2E, fp16)
//  blocks [256,512):    input -> g_kh (normalize, transpose, fp16)
//  blocks [512,1536):   input -> g_vh (fp16 convert, layout preserved)
//  blocks [1536,1600):  weight -> g_wh/g_wl ([o][c] hi/lo) + BN constants
// ---------------------------------------------------------------------------
__global__ __launch_bounds__(256, 1)
void prep_all(const float* __restrict__ input, const float* __restrict__ tg,
              const float* __restrict__ w, const float* __restrict__ gamma,
              const float* __restrict__ beta, const float* __restrict__ rmean,
              const float* __restrict__ rvar) {
    int blk = blockIdx.x;
    int tid = threadIdx.x;

    if (blk < 512) {
        const float* x;
        __half* dst;
        float esc;
        int lb;
        if (blk < 256) { x = tg;    dst = g_qh; esc = LOG2E; lb = blk; }
        else           { x = input; dst = g_kh; esc = 1.0f;  lb = blk - 256; }
        float* t  = (float*)dyn_smem;              // [128][129]
        float* rn = t + 128 * 129;
        int b = lb >> 5, l0 = (lb & 31) * 128;
        const float* src = x + (size_t)b * C_ * 4096 + l0;
        for (int idx = tid; idx < 128 * 128; idx += 256) {
            int c = idx >> 7, l = idx & 127;
            t[c * 129 + l] = src[(size_t)c * 4096 + l];
        }
        __syncthreads();
        if (tid < 128) {
            float s = 0.f;
#pragma unroll 8
            for (int c = 0; c < 128; c++) { float v = t[c * 129 + tid]; s += v * v; }
            rn[tid] = esc / fmaxf(sqrtf(s), 1e-12f);
        }
        __syncthreads();
        for (int idx = tid; idx < 128 * 128; idx += 256) {
            int l = idx >> 7, c = idx & 127;
            float v = t[c * 129 + l] * rn[l];
            dst[((size_t)b * 4096 + l0 + l) * C_ + c] = __float2half_rn(v);
        }
    } else if (blk < 1536) {
        size_t i = (size_t)(blk - 512) * 256 + tid;
        for (; i < (size_t)B_ * C_ * N_ / 4; i += 1024 * 256) {
            float4 v = ((const float4*)input)[i];
            ((uint2*)g_vh)[i] = make_uint2(pack_h2(v.x, v.y), pack_h2(v.z, v.w));
        }
    } else {
        int i = (blk - 1536) * 256 + tid;       // 0 .. 16383
        if (i < C_ * OUT_) {
            int c = i / OUT_, o = i % OUT_;     // w is [c][o]; read coalesced
            float v = w[i];
            __half h = __float2half_rn(v);
            g_wh[o * C_ + c] = h;               // store [o][c]
            g_wl[o * C_ + c] = __float2half_rn(v - __half2float(h));
        }
        if (i < OUT_) {
            float s = rsqrtf(rvar[i] + 1e-5f) * gamma[i];
            g_sc[i] = s;
            g_bi[i] = beta[i] - rmean[i] * s;
        }
    }
}

// ---------------------------------------------------------------------------
// Pure-fp16 HMMA flash attention + fused projection/LeakyReLU/BN epilogue.
// grid = B*(M/128)=256, 256 threads (8 warps, 16 m-rows each).
// N-tile 128, double-buffered K/V via cp.async. Q fragments register-resident.
// fp32 S accumulators + batched f16x2 exp (R14 structure).
// smem: Q 32K | 2 x { K 32K | V 32K } | Whi 32K | Wlo 32K = 224K, 1 CTA/SM
// ---------------------------------------------------------------------------
#define SMQ  0
#define SMKV 32768
#define SMWH 163840
#define SMWL 196608
#define ATTN_SMEM 229376

__global__ __launch_bounds__(256, 1)
void attn_mma_kernel(float* __restrict__ out) {
    char* smc = dyn_smem;
    uint32_t sbase = smem_u32(smc);

    int tid = threadIdx.x;
    int w = tid >> 5, ln = tid & 31;
    int b  = blockIdx.x >> 5;
    int m0 = (blockIdx.x & 31) * 128;

    // ---- load Q tile [128m][128c] and W hi/lo [128o][128c] (once) ----
    {
        const uint4* qg = (const uint4*)(g_qh + ((size_t)b * M_ + m0) * C_);
        const uint4* whg = (const uint4*)g_wh;
        const uint4* wlg = (const uint4*)g_wl;
        for (int idx = tid; idx < 2048; idx += 256) {
            int row = idx >> 4, ch = idx & 15;
            uint32_t off = row * 256 + ((ch ^ (row & 7)) << 4);
            *(uint4*)(smc + SMQ + off)  = qg[row * 16 + ch];
            *(uint4*)(smc + SMWH + off) = whg[row * 16 + ch];
            *(uint4*)(smc + SMWL + off) = wlg[row * 16 + ch];
        }
    }

    // tile loader: K [128n][128c] + V [128c][128n], both 256B rows
    auto issue_tiles = [&](int buf, int it) {
        int n0 = it * 128;
        uint32_t kb = sbase + SMKV + buf * 65536;
        const char* kg = (const char*)(g_kh + ((size_t)b * N_ + n0) * C_);
#pragma unroll
        for (int i = 0; i < 8; i++) {
            int idx = tid + i * 256;
            int row = idx >> 4, ch = idx & 15;
            uint32_t off = row * 256 + ((ch ^ (row & 7)) << 4);
            cpasync16(kb + off, kg + row * 256 + ch * 16);
        }
        const char* vg = (const char*)(g_vh + (size_t)b * C_ * N_ + n0);
#pragma unroll
        for (int i = 0; i < 8; i++) {
            int idx = tid + i * 256;
            int row = idx >> 4, ch = idx & 15;
            uint32_t off = row * 256 + ((ch ^ (row & 7)) << 4);
            cpasync16(kb + 32768 + off, vg + (size_t)row * 8192 + ch * 16);
        }
    };

    issue_tiles(0, 0);
    CP_COMMIT();
    __syncthreads();      // Q smem stores visible

    // ---- hoist Q fragments to registers for the whole kernel ----
    uint32_t qfrag[8][4];
#pragma unroll
    for (int ks = 0; ks < 8; ks++) {
        int r = 16 * w + (ln & 15);
        int ch = 2 * ks + (ln >> 4);
        uint32_t off = r * 256 + ((ch ^ (r & 7)) << 4);
        ldsm4(qfrag[ks], sbase + SMQ + off);
    }

    float oacc[16][4];
#pragma unroll
    for (int i = 0; i < 16; i++)
#pragma unroll
        for (int j = 0; j < 4; j++) oacc[i][j] = 0.f;
    float rs0 = 0.f, rs1 = 0.f;

    for (int it = 0; it < 32; it++) {
        int buf = it & 1;
        __syncthreads();                       // prev reads of buf^1 done
        if (it + 1 < 32) issue_tiles(buf ^ 1, it + 1);
        CP_COMMIT();
        CP_WAIT1();                            // tile `it` landed
        __syncthreads();

        uint32_t kbase = sbase + SMKV + buf * 65536;
        uint32_t vbase = kbase + 32768;

        // ---- S = Q.K^T  [16m x 128n per warp], fp32 accumulators ----
        float sacc[16][4];
#pragma unroll
        for (int i = 0; i < 16; i++)
#pragma unroll
            for (int j = 0; j < 4; j++) sacc[i][j] = 0.f;

#pragma unroll
        for (int ks = 0; ks < 8; ks++) {
#pragma unroll
            for (int p = 0; p < 8; p++) {
                uint32_t bh[4];
                int r = 16 * p + ((ln >> 4) << 3) + (ln & 7);
                int ch = 2 * ks + ((ln >> 3) & 1);
                uint32_t off = r * 256 + ((ch ^ (r & 7)) << 4);
                ldsm4(bh, kbase + off);
                mma16816(sacc[2*p],   qfrag[ks], bh);
                mma16816(sacc[2*p+1], qfrag[ks], bh + 2);
            }
        }

        // ---- P = exp2(S) via f16x2 MUFU (max-free: scores bounded, fp16-safe) ----
        uint32_t phi[16][2];
#pragma unroll
        for (int nb = 0; nb < 16; nb++) {
            phi[nb][0] = ex2_h2(pack_h2(sacc[nb][0], sacc[nb][1]));
            phi[nb][1] = ex2_h2(pack_h2(sacc[nb][2], sacc[nb][3]));
        }
        // row sums: 2-level fp16 tree (4-sums), then fp32 accumulate
#pragma unroll
        for (int g = 0; g < 4; g++) {
            uint32_t a0 = hadd2_(hadd2_(phi[4*g][0], phi[4*g+1][0]),
                                 hadd2_(phi[4*g+2][0], phi[4*g+3][0]));
            float2 f0 = h2_to_f2(a0);
            rs0 += f0.x + f0.y;
            uint32_t a1 = hadd2_(hadd2_(phi[4*g][1], phi[4*g+1][1]),
                                 hadd2_(phi[4*g+2][1], phi[4*g+3][1]));
            float2 f1 = h2_to_f2(a1);
            rs1 += f1.x + f1.y;
        }

        // ---- O += P.V^T  [16m x 128c per warp, contract n=128] ----
#pragma unroll
        for (int kn = 0; kn < 8; kn++) {
            uint32_t ah[4] = {phi[2*kn][0], phi[2*kn][1], phi[2*kn+1][0], phi[2*kn+1][1]};
#pragma unroll
            for (int g = 0; g < 2; g++) {
#pragma unroll
                for (int p = 0; p < 4; p++) {
                    uint32_t vh[4];
                    int r = 16 * (4 * g + p) + ((ln >> 4) << 3) + (ln & 7);
                    int ch = 2 * kn + ((ln >> 3) & 1);
                    uint32_t off = r * 256 + ((ch ^ (r & 7)) << 4);
                    ldsm4(vh, vbase + off);
                    int cb = 8 * g + 2 * p;
                    mma16816(oacc[cb],     ah, vh);
                    mma16816(oacc[cb + 1], ah, vh + 2);
                }
            }
        }
    }

    // =================== fused epilogue ===================
    rs0 += __shfl_xor_sync(0xffffffffu, rs0, 1);
    rs0 += __shfl_xor_sync(0xffffffffu, rs0, 2);
    rs1 += __shfl_xor_sync(0xffffffffu, rs1, 1);
    rs1 += __shfl_xor_sync(0xffffffffu, rs1, 2);
    float inv0 = 1.0f / rs0, inv1 = 1.0f / rs1;

    // pack O/l hi + residual lo (same frag layout as mainloop P)
    uint32_t ohi[16][2], olo[16][2];
#pragma unroll
    for (int nb = 0; nb < 16; nb++) {
        float e0 = oacc[nb][0] * inv0;
        float e1 = oacc[nb][1] * inv0;
        float e2 = oacc[nb][2] * inv1;
        float e3 = oacc[nb][3] * inv1;
        __half h0 = __float2half_rn(e0), h1 = __float2half_rn(e1);
        __half h2 = __float2half_rn(e2), h3 = __float2half_rn(e3);
        ohi[nb][0] = (uint32_t)*(unsigned short*)&h0 | ((uint32_t)*(unsigned short*)&h1 << 16);
        ohi[nb][1] = (uint32_t)*(unsigned short*)&h2 | ((uint32_t)*(unsigned short*)&h3 << 16);
        olo[nb][0] = pack_h2(e0 - __half2float(h0), e1 - __half2float(h1));
        olo[nb][1] = pack_h2(e2 - __half2float(h2), e3 - __half2float(h3));
    }

    // epi MMA: z[16m][128o] = (O/l) . W   (W tile is [o][c]: B rows = o, cols = c)
    float eacc[16][4];
#pragma unroll
    for (int i = 0; i < 16; i++)
#pragma unroll
        for (int j = 0; j < 4; j++) eacc[i][j] = 0.f;

#pragma unroll
    for (int kc = 0; kc < 8; kc++) {
        uint32_t ah[4] = {ohi[2*kc][0], ohi[2*kc][1], ohi[2*kc+1][0], ohi[2*kc+1][1]};
        uint32_t al[4] = {olo[2*kc][0], olo[2*kc][1], olo[2*kc+1][0], olo[2*kc+1][1]};
#pragma unroll
        for (int p = 0; p < 8; p++) {
            int r = 16 * p + ((ln >> 4) << 3) + (ln & 7);
            int ch = 2 * kc + ((ln >> 3) & 1);
            uint32_t off = r * 256 + ((ch ^ (r & 7)) << 4);
            uint32_t wh[4], wl[4];
            ldsm4(wh, sbase + SMWH + off);
            ldsm4(wl, sbase + SMWL + off);
            mma16816(eacc[2*p],   ah, wh);
            mma16816(eacc[2*p+1], ah, wh + 2);
            mma16816(eacc[2*p],   ah, wl);
            mma16816(eacc[2*p+1], ah, wl + 2);
            mma16816(eacc[2*p],   al, wh);
            mma16816(eacc[2*p+1], al, wh + 2);
        }
    }

    // LeakyReLU + BN, scatter to stage [128o][132m] (reuses KV smem)
    __syncthreads();            // all warps done with last V tile before overwrite
    float* stage = (float*)(smc + SMKV);
    int r0 = 16 * w + (ln >> 2);
    int r1 = r0 + 8;
#pragma unroll
    for (int cb = 0; cb < 16; cb++) {
        int o0c = 8 * cb + 2 * (ln & 3);
        float s0 = g_sc[o0c],     b0 = g_bi[o0c];
        float s1 = g_sc[o0c + 1], b1 = g_bi[o0c + 1];
        float z0 = eacc[cb][0]; z0 = (z0 >= 0.f) ? z0 : 0.01f * z0;
        float z1 = eacc[cb][1]; z1 = (z1 >= 0.f) ? z1 : 0.01f * z1;
        float z2 = eacc[cb][2]; z2 = (z2 >= 0.f) ? z2 : 0.01f * z2;
        float z3 = eacc[cb][3]; z3 = (z3 >= 0.f) ? z3 : 0.01f * z3;
        stage[o0c * 132 + r0]       = z0 * s0 + b0;
        stage[(o0c + 1) * 132 + r0] = z1 * s1 + b1;
        stage[o0c * 132 + r1]       = z2 * s0 + b0;
        stage[(o0c + 1) * 132 + r1] = z3 * s1 + b1;
    }
    __syncthreads();

    // coalesced write: out[b][o][m0 + m]
    float* dst = out + ((size_t)b * OUT_) * M_ + m0;
    for (int idx = tid; idx < 128 * 32; idx += 256) {
        int o = idx >> 5, m4 = idx & 31;
        *(float4*)(dst + (size_t)o * M_ + 4 * m4) = *(float4*)(stage + o * 132 + 4 * m4);
    }
}

// ---------------------------------------------------------------------------
extern "C" void kernel_launch(void* const* d_in, const int* in_sizes, int n_in,
                              void* d_out, int out_size) {
    const float* input  = (const float*)d_in[0];
    const float* tg     = (const float*)d_in[1];
    const float* weight = (const float*)d_in[2];
    const float* gamma  = (const float*)d_in[3];
    const float* beta   = (const float*)d_in[4];
    const float* rmean  = (const float*)d_in[5];
    const float* rvar   = (const float*)d_in[6];
    float* out = (float*)d_out;

    const int prep_smem = (128 * 129 + 128) * (int)sizeof(float);
    cudaFuncSetAttribute(prep_all, cudaFuncAttributeMaxDynamicSharedMemorySize, prep_smem);
    cudaFuncSetAttribute(attn_mma_kernel, cudaFuncAttributeMaxDynamicSharedMemorySize, ATTN_SMEM);

    prep_all<<<1600, 256, prep_smem>>>(input, tg, weight, gamma, beta, rmean, rvar);
    attn_mma_kernel<<<B_ * (M_ / 128), 256, ATTN_SMEM>>>(out);
}

// round 17
// speedup vs baseline: 1.5272x; 1.0392x over previous
#include <cuda_runtime.h>
#include <cuda_fp16.h>
#include <cstdint>

#define B_    8
#define C_    128
#define N_    4096
#define M_    4096
#define OUT_  128
#define LOG2E 1.4426950408889634f

extern __shared__ char dyn_smem[];

__device__ __half g_qh[(size_t)B_ * M_ * C_];   // [b][m][c] normalized*log2e (fp16)
__device__ __half g_kh[(size_t)B_ * N_ * C_];   // [b][n][c] normalized (fp16)
__device__ __half g_vh[(size_t)B_ * C_ * N_];   // [b][c][n] raw fp16
__device__ __half g_wh[C_ * OUT_];              // [o][c] weight (transposed for MMA B)
__device__ float  g_sc[OUT_];                   // BN scale
__device__ float  g_bi[OUT_];                   // BN bias

__device__ __forceinline__ uint32_t smem_u32(const void* p) {
    uint32_t a;
    asm("{ .reg .u64 t; cvta.to.shared.u64 t, %1; cvt.u32.u64 %0, t; }" : "=r"(a) : "l"(p));
    return a;
}
__device__ __forceinline__ void ldsm4(uint32_t* r, uint32_t addr) {
    asm volatile("ldmatrix.sync.aligned.m8n8.x4.shared.b16 {%0,%1,%2,%3}, [%4];"
                 : "=r"(r[0]), "=r"(r[1]), "=r"(r[2]), "=r"(r[3]) : "r"(addr));
}
__device__ __forceinline__ void mma16816(float* d, const uint32_t* a, const uint32_t* b) {
    asm volatile("mma.sync.aligned.m16n8k16.row.col.f32.f16.f16.f32 "
                 "{%0,%1,%2,%3}, {%4,%5,%6,%7}, {%8,%9}, {%0,%1,%2,%3};"
                 : "+f"(d[0]), "+f"(d[1]), "+f"(d[2]), "+f"(d[3])
                 : "r"(a[0]), "r"(a[1]), "r"(a[2]), "r"(a[3]), "r"(b[0]), "r"(b[1]));
}
__device__ __forceinline__ void cpasync16(uint32_t saddr, const void* gaddr) {
    asm volatile("cp.async.cg.shared.global [%0], [%1], 16;" :: "r"(saddr), "l"(gaddr));
}
#define CP_COMMIT() asm volatile("cp.async.commit_group;" ::: "memory")
#define CP_WAIT1()  asm volatile("cp.async.wait_group 1;" ::: "memory")
#define CP_WAIT0()  asm volatile("cp.async.wait_group 0;" ::: "memory")
__device__ __forceinline__ uint32_t pack_h2(float lo, float hi) {
    __half2 h = __floats2half2_rn(lo, hi);
    return *(uint32_t*)&h;
}
__device__ __forceinline__ uint32_t ex2_h2(uint32_t x) {
    uint32_t r;
    asm("ex2.approx.f16x2 %0, %1;" : "=r"(r) : "r"(x));
    return r;
}
__device__ __forceinline__ uint32_t hadd2_(uint32_t a, uint32_t b) {
    uint32_t r;
    asm("add.f16x2 %0, %1, %2;" : "=r"(r) : "r"(a), "r"(b));
    return r;
}
__device__ __forceinline__ float2 h2_to_f2(uint32_t a) {
    __half2 h = *(__half2*)&a;
    return __half22float2(h);
}

// ---------------------------------------------------------------------------
// merged prep kernel (block-range dispatch)
// ---------------------------------------------------------------------------
__global__ __launch_bounds__(256, 1)
void prep_all(const float* __restrict__ input, const float* __restrict__ tg,
              const float* __restrict__ w, const float* __restrict__ gamma,
              const float* __restrict__ beta, const float* __restrict__ rmean,
              const float* __restrict__ rvar) {
    int blk = blockIdx.x;
    int tid = threadIdx.x;

    if (blk < 512) {
        const float* x;
        __half* dst;
        float esc;
        int lb;
        if (blk < 256) { x = tg;    dst = g_qh; esc = LOG2E; lb = blk; }
        else           { x = input; dst = g_kh; esc = 1.0f;  lb = blk - 256; }
        float* t  = (float*)dyn_smem;              // [128][129]
        float* rn = t + 128 * 129;
        int b = lb >> 5, l0 = (lb & 31) * 128;
        const float* src = x + (size_t)b * C_ * 4096 + l0;
        for (int idx = tid; idx < 128 * 128; idx += 256) {
            int c = idx >> 7, l = idx & 127;
            t[c * 129 + l] = src[(size_t)c * 4096 + l];
        }
        __syncthreads();
        if (tid < 128) {
            float s = 0.f;
#pragma unroll 8
            for (int c = 0; c < 128; c++) { float v = t[c * 129 + tid]; s += v * v; }
            rn[tid] = esc / fmaxf(sqrtf(s), 1e-12f);
        }
        __syncthreads();
        for (int idx = tid; idx < 128 * 128; idx += 256) {
            int l = idx >> 7, c = idx & 127;
            float v = t[c * 129 + l] * rn[l];
            dst[((size_t)b * 4096 + l0 + l) * C_ + c] = __float2half_rn(v);
        }
    } else if (blk < 1536) {
        size_t i = (size_t)(blk - 512) * 256 + tid;
        for (; i < (size_t)B_ * C_ * N_ / 4; i += 1024 * 256) {
            float4 v = ((const float4*)input)[i];
            ((uint2*)g_vh)[i] = make_uint2(pack_h2(v.x, v.y), pack_h2(v.z, v.w));
        }
    } else {
        int i = (blk - 1536) * 256 + tid;
        if (i < C_ * OUT_) {
            int c = i / OUT_, o = i % OUT_;
            g_wh[o * C_ + c] = __float2half_rn(w[i]);
        }
        if (i < OUT_) {
            float s = rsqrtf(rvar[i] + 1e-5f) * gamma[i];
            g_sc[i] = s;
            g_bi[i] = beta[i] - rmean[i] * s;
        }
    }
}

// ---------------------------------------------------------------------------
// Triple-buffered fp16 HMMA flash attention + fused epilogue.
// smem: Q 32K | 3 x { K 32K | V 32K } = 224K, 1 CTA/SM, 1 sync/iter.
// W streamed into buf2 at iter 30; stage uses buf0/buf1.
// ---------------------------------------------------------------------------
#define SMQ  0
#define SMKV 32768
#define BUFSZ 65536
#define ATTN_SMEM 229376

__global__ __launch_bounds__(256, 1)
void attn_mma_kernel(float* __restrict__ out) {
    char* smc = dyn_smem;
    uint32_t sbase = smem_u32(smc);

    int tid = threadIdx.x;
    int w = tid >> 5, ln = tid & 31;
    int b  = blockIdx.x >> 5;
    int m0 = (blockIdx.x & 31) * 128;

    {
        const uint4* qg = (const uint4*)(g_qh + ((size_t)b * M_ + m0) * C_);
        for (int idx = tid; idx < 2048; idx += 256) {
            int row = idx >> 4, ch = idx & 15;
            uint32_t off = row * 256 + ((ch ^ (row & 7)) << 4);
            *(uint4*)(smc + SMQ + off) = qg[row * 16 + ch];
        }
    }

    auto issue_tiles = [&](int it) {
        int n0 = it * 128;
        uint32_t kb = sbase + SMKV + (it % 3) * BUFSZ;
        const char* kg = (const char*)(g_kh + ((size_t)b * N_ + n0) * C_);
#pragma unroll
        for (int i = 0; i < 8; i++) {
            int idx = tid + i * 256;
            int row = idx >> 4, ch = idx & 15;
            uint32_t off = row * 256 + ((ch ^ (row & 7)) << 4);
            cpasync16(kb + off, kg + row * 256 + ch * 16);
        }
        const char* vg = (const char*)(g_vh + (size_t)b * C_ * N_ + n0);
#pragma unroll
        for (int i = 0; i < 8; i++) {
            int idx = tid + i * 256;
            int row = idx >> 4, ch = idx & 15;
            uint32_t off = row * 256 + ((ch ^ (row & 7)) << 4);
            cpasync16(kb + 32768 + off, vg + (size_t)row * 8192 + ch * 16);
        }
    };
    auto issue_w = [&]() {
        uint32_t wb = sbase + SMKV + 2 * BUFSZ;   // buf2 (tile 29's buffer, freed)
#pragma unroll
        for (int i = 0; i < 8; i++) {
            int idx = tid + i * 256;
            int row = idx >> 4, ch = idx & 15;
            uint32_t off = row * 256 + ((ch ^ (row & 7)) << 4);
            cpasync16(wb + off, (const char*)g_wh + row * 256 + ch * 16);
        }
    };

    issue_tiles(0); CP_COMMIT();
    issue_tiles(1); CP_COMMIT();
    __syncthreads();                 // Q stores visible

    uint32_t qfrag[8][4];
#pragma unroll
    for (int ks = 0; ks < 8; ks++) {
        int r = 16 * w + (ln & 15);
        int ch = 2 * ks + (ln >> 4);
        uint32_t off = r * 256 + ((ch ^ (r & 7)) << 4);
        ldsm4(qfrag[ks], sbase + SMQ + off);
    }

    float oacc[16][4];
#pragma unroll
    for (int i = 0; i < 16; i++)
#pragma unroll
        for (int j = 0; j < 4; j++) oacc[i][j] = 0.f;
    float rs0 = 0.f, rs1 = 0.f;

    for (int it = 0; it < 32; it++) {
        CP_WAIT1();                 // tile `it` landed (own groups)
        __syncthreads();            // global: tile landed; iter it-1 reads fenced

        if (it < 30)       { issue_tiles(it + 2); CP_COMMIT(); }
        else if (it == 30) { issue_w();           CP_COMMIT(); }

        uint32_t kbase = sbase + SMKV + (it % 3) * BUFSZ;
        uint32_t vbase = kbase + 32768;

        float sacc[16][4];
#pragma unroll
        for (int i = 0; i < 16; i++)
#pragma unroll
            for (int j = 0; j < 4; j++) sacc[i][j] = 0.f;

#pragma unroll
        for (int ks = 0; ks < 8; ks++) {
#pragma unroll
            for (int p = 0; p < 8; p++) {
                uint32_t bh[4];
                int r = 16 * p + ((ln >> 4) << 3) + (ln & 7);
                int ch = 2 * ks + ((ln >> 3) & 1);
                uint32_t off = r * 256 + ((ch ^ (r & 7)) << 4);
                ldsm4(bh, kbase + off);
                mma16816(sacc[2*p],   qfrag[ks], bh);
                mma16816(sacc[2*p+1], qfrag[ks], bh + 2);
            }
        }

        uint32_t phi[16][2];
#pragma unroll
        for (int nb = 0; nb < 16; nb++) {
            phi[nb][0] = ex2_h2(pack_h2(sacc[nb][0], sacc[nb][1]));
            phi[nb][1] = ex2_h2(pack_h2(sacc[nb][2], sacc[nb][3]));
        }
#pragma unroll
        for (int g = 0; g < 4; g++) {
            uint32_t a0 = hadd2_(hadd2_(phi[4*g][0], phi[4*g+1][0]),
                                 hadd2_(phi[4*g+2][0], phi[4*g+3][0]));
            float2 f0 = h2_to_f2(a0);
            rs0 += f0.x + f0.y;
            uint32_t a1 = hadd2_(hadd2_(phi[4*g][1], phi[4*g+1][1]),
                                 hadd2_(phi[4*g+2][1], phi[4*g+3][1]));
            float2 f1 = h2_to_f2(a1);
            rs1 += f1.x + f1.y;
        }

#pragma unroll
        for (int kn = 0; kn < 8; kn++) {
            uint32_t ah[4] = {phi[2*kn][0], phi[2*kn][1], phi[2*kn+1][0], phi[2*kn+1][1]};
#pragma unroll
            for (int g = 0; g < 2; g++) {
#pragma unroll
                for (int p = 0; p < 4; p++) {
                    uint32_t vh[4];
                    int r = 16 * (4 * g + p) + ((ln >> 4) << 3) + (ln & 7);
                    int ch = 2 * kn + ((ln >> 3) & 1);
                    uint32_t off = r * 256 + ((ch ^ (r & 7)) << 4);
                    ldsm4(vh, vbase + off);
                    int cb = 8 * g + 2 * p;
                    mma16816(oacc[cb],     ah, vh);
                    mma16816(oacc[cb + 1], ah, vh + 2);
                }
            }
        }
    }

    // =================== fused epilogue ===================
    CP_WAIT0();                     // W landed
    __syncthreads();

    rs0 += __shfl_xor_sync(0xffffffffu, rs0, 1);
    rs0 += __shfl_xor_sync(0xffffffffu, rs0, 2);
    rs1 += __shfl_xor_sync(0xffffffffu, rs1, 1);
    rs1 += __shfl_xor_sync(0xffffffffu, rs1, 2);
    float inv0 = 1.0f / rs0, inv1 = 1.0f / rs1;

    uint32_t ohi[16][2], olo[16][2];
#pragma unroll
    for (int nb = 0; nb < 16; nb++) {
        float e0 = oacc[nb][0] * inv0;
        float e1 = oacc[nb][1] * inv0;
        float e2 = oacc[nb][2] * inv1;
        float e3 = oacc[nb][3] * inv1;
        __half h0 = __float2half_rn(e0), h1 = __float2half_rn(e1);
        __half h2 = __float2half_rn(e2), h3 = __float2half_rn(e3);
        ohi[nb][0] = (uint32_t)*(unsigned short*)&h0 | ((uint32_t)*(unsigned short*)&h1 << 16);
        ohi[nb][1] = (uint32_t)*(unsigned short*)&h2 | ((uint32_t)*(unsigned short*)&h3 << 16);
        olo[nb][0] = pack_h2(e0 - __half2float(h0), e1 - __half2float(h1));
        olo[nb][1] = pack_h2(e2 - __half2float(h2), e3 - __half2float(h3));
    }

    uint32_t wbase = sbase + SMKV + 2 * BUFSZ;
    float eacc[16][4];
#pragma unroll
    for (int i = 0; i < 16; i++)
#pragma unroll
        for (int j = 0; j < 4; j++) eacc[i][j] = 0.f;

#pragma unroll
    for (int kc = 0; kc < 8; kc++) {
        uint32_t ah[4] = {ohi[2*kc][0], ohi[2*kc][1], ohi[2*kc+1][0], ohi[2*kc+1][1]};
        uint32_t al[4] = {olo[2*kc][0], olo[2*kc][1], olo[2*kc+1][0], olo[2*kc+1][1]};
#pragma unroll
        for (int p = 0; p < 8; p++) {
            int r = 16 * p + ((ln >> 4) << 3) + (ln & 7);
            int ch = 2 * kc + ((ln >> 3) & 1);
            uint32_t off = r * 256 + ((ch ^ (r & 7)) << 4);
            uint32_t wh[4];
            ldsm4(wh, wbase + off);
            mma16816(eacc[2*p],   ah, wh);
            mma16816(eacc[2*p+1], ah, wh + 2);
            mma16816(eacc[2*p],   al, wh);
            mma16816(eacc[2*p+1], al, wh + 2);
        }
    }

    __syncthreads();
    float* stage = (float*)(smc + SMKV);    // buf0+buf1 free (W is in buf2)
    int r0 = 16 * w + (ln >> 2);
    int r1 = r0 + 8;
#pragma unroll
    for (int cb = 0; cb < 16; cb++) {
        int o0c = 8 * cb + 2 * (ln & 3);
        float s0 = g_sc[o0c],     b0 = g_bi[o0c];
        float s1 = g_sc[o0c + 1], b1 = g_bi[o0c + 1];
        float z0 = eacc[cb][0]; z0 = (z0 >= 0.f) ? z0 : 0.01f * z0;
        float z1 = eacc[cb][1]; z1 = (z1 >= 0.f) ? z1 : 0.01f * z1;
        float z2 = eacc[cb][2]; z2 = (z2 >= 0.f) ? z2 : 0.01f * z2;
        float z3 = eacc[cb][3]; z3 = (z3 >= 0.f) ? z3 : 0.01f * z3;
        stage[o0c * 132 + r0]       = z0 * s0 + b0;
        stage[(o0c + 1) * 132 + r0] = z1 * s1 + b1;
        stage[o0c * 132 + r1]       = z2 * s0 + b0;
        stage[(o0c + 1) * 132 + r1] = z3 * s1 + b1;
    }
    __syncthreads();

    float* dst = out + ((size_t)b * OUT_) * M_ + m0;
    for (int idx = tid; idx < 128 * 32; idx += 256) {
        int o = idx >> 5, m4 = idx & 31;
        *(float4*)(dst + (size_t)o * M_ + 4 * m4) = *(float4*)(stage + o * 132 + 4 * m4);
    }
}

// ---------------------------------------------------------------------------
extern "C" void kernel_launch(void* const* d_in, const int* in_sizes, int n_in,
                              void* d_out, int out_size) {
    const float* input  = (const float*)d_in[0];
    const float* tg     = (const float*)d_in[1];
    const float* weight = (const float*)d_in[2];
    const float* gamma  = (const float*)d_in[3];
    const float* beta   = (const float*)d_in[4];
    const float* rmean  = (const float*)d_in[5];
    const float* rvar   = (const float*)d_in[6];
    float* out = (float*)d_out;

    const int prep_smem = (128 * 129 + 128) * (int)sizeof(float);
    cudaFuncSetAttribute(prep_all, cudaFuncAttributeMaxDynamicSharedMemorySize, prep_smem);
    cudaFuncSetAttribute(attn_mma_kernel, cudaFuncAttributeMaxDynamicSharedMemorySize, ATTN_SMEM);

    prep_all<<<1600, 256, prep_smem>>>(input, tg, weight, gamma, beta, rmean, rvar);
    attn_mma_kernel<<<B_ * (M_ / 128), 256, ATTN_SMEM>>>(out);
}